// round 15
// baseline (speedup 1.0000x reference)
#include <cuda_runtime.h>
#include <cuda_fp16.h>
#include <cstdint>

// ---------------------------------------------------------------------------
// PolyActGCN: CSR build (vec4) -> agg(->fp16) -> GEMM(fp16 A, W hi+lo, 2-pass
// HMMA, fused stats->g_part) -> bnfin -> bnpoly(->fp16) -> ... -> GEMM(+b3)
// ---------------------------------------------------------------------------

#define NMAX 131072
#define EMAX 2097152
typedef unsigned long long ull;

__device__ float  g_bufB[(size_t)NMAX * 128];    // fp32 GEMM output
__device__ __half g_hbufA[(size_t)NMAX * 128];   // fp16 agg output (GEMM A)
__device__ __half g_hbuf[(size_t)NMAX * 128];    // fp16 activations
__device__ int    g_deg[NMAX];           // invariant: zero at launch entry
__device__ int    g_cur[NMAX];
__device__ int    g_off[NMAX + 1];
__device__ int2   g_edge[EMAX];
__device__ ull    g_epoch;
__device__ ull    g_pub[128];
__device__ ull    g_wpk[3 * 8192];       // [layer][part][s][nt][lane] fp16x4
__device__ float  g_part[296 * 256];     // per-block stats partials
__device__ float  g_scale[128];
__device__ float  g_shift[128];

// ---------------- helpers --------------------------------------------------
static __device__ __forceinline__ ull pack2(float x, float y) {
    ull p;
    asm("mov.b64 %0, {%1, %2};" : "=l"(p)
        : "r"(__float_as_uint(x)), "r"(__float_as_uint(y)));
    return p;
}
static __device__ __forceinline__ float2 unpack2(ull p) {
    unsigned int a, b;
    asm("mov.b64 {%0, %1}, %2;" : "=r"(a), "=r"(b) : "l"(p));
    return make_float2(__uint_as_float(a), __uint_as_float(b));
}
static __device__ __forceinline__ ull ffma2(ull a, ull b, ull c) {
    ull d;
    asm("fma.rn.f32x2 %0, %1, %2, %3;" : "=l"(d) : "l"(a), "l"(b), "l"(c));
    return d;
}
static __device__ __forceinline__ uint32_t smem_u32(const void* p) {
    uint32_t a;
    asm("{ .reg .u64 t; cvta.to.shared.u64 t, %1; cvt.u32.u64 %0, t; }"
        : "=r"(a) : "l"(p));
    return a;
}

// ---------------- CSR build (4 edges / thread) -----------------------------
__global__ void k_count(const int* __restrict__ row, int E) {
    if (blockIdx.x == 0 && threadIdx.x == 0) atomicAdd(&g_epoch, 1ULL);
    int i = (blockIdx.x * 256 + threadIdx.x) << 2;
    if (i + 4 <= E) {
        int4 r = __ldcs((const int4*)&row[i]);
        atomicAdd(&g_deg[r.x], 1);
        atomicAdd(&g_deg[r.y], 1);
        atomicAdd(&g_deg[r.z], 1);
        atomicAdd(&g_deg[r.w], 1);
    } else {
        for (; i < E; i++) atomicAdd(&g_deg[__ldcs(&row[i])], 1);
    }
}

__global__ void k_scan(int nb, int N) {
    __shared__ int sh[256];
    __shared__ int bsum[128];
    int b = blockIdx.x, t = threadIdx.x;
    ull epoch = g_epoch;
    int idx = (b << 8) + t;
    int4 d4 = ((const int4*)g_deg)[idx];
    ((int4*)g_deg)[idx] = make_int4(0, 0, 0, 0);
    int s0 = d4.x, s1 = s0 + d4.y, s2 = s1 + d4.z, s3 = s2 + d4.w;
    sh[t] = s3;
    __syncthreads();
    for (int d = 1; d < 256; d <<= 1) {
        int u = (t >= d) ? sh[t - d] : 0;
        __syncthreads();
        sh[t] += u;
        __syncthreads();
    }
    if (t == 0) atomicExch(&g_pub[b], (epoch << 32) | (unsigned)sh[255]);
    if (t < nb) {
        ull v;
        do { v = *(volatile ull*)&g_pub[t]; } while ((v >> 32) != (epoch & 0xffffffffULL));
        bsum[t] = (int)(v & 0xffffffffULL);
    }
    __syncthreads();
    int pre = 0;
    for (int j = 0; j < b; j++) pre += bsum[j];
    if (b == 0 && t == 0) {
        int tot = 0;
        for (int j = 0; j < nb; j++) tot += bsum[j];
        g_off[N] = tot;
    }
    int pr = pre + sh[t] - s3;
    int4 o4 = make_int4(pr, pr + s0, pr + s1, pr + s2);
    ((int4*)g_off)[idx] = o4;
    ((int4*)g_cur)[idx] = o4;
}

__global__ void k_fill(const int* __restrict__ row, const int* __restrict__ col,
                       const float* __restrict__ ew, int E) {
    int i = (blockIdx.x * 256 + threadIdx.x) << 2;
    if (i + 4 <= E) {
        int4 r = __ldcs((const int4*)&row[i]);
        int4 c = __ldcs((const int4*)&col[i]);
        float4 w = __ldcs((const float4*)&ew[i]);
        int p0 = atomicAdd(&g_cur[r.x], 1);
        int p1 = atomicAdd(&g_cur[r.y], 1);
        int p2 = atomicAdd(&g_cur[r.z], 1);
        int p3 = atomicAdd(&g_cur[r.w], 1);
        g_edge[p0] = make_int2(c.x, __float_as_int(w.x));
        g_edge[p1] = make_int2(c.y, __float_as_int(w.y));
        g_edge[p2] = make_int2(c.z, __float_as_int(w.z));
        g_edge[p3] = make_int2(c.w, __float_as_int(w.w));
    } else {
        for (; i < E; i++) {
            int p = atomicAdd(&g_cur[__ldcs(&row[i])], 1);
            g_edge[p] = make_int2(__ldcs(&col[i]), __float_as_int(__ldcs(&ew[i])));
        }
    }
}

// ---------------- aggregation (fp32 source, layer 1) -> fp16 out -----------
__global__ void __launch_bounds__(256)
k_agg(const float* __restrict__ x, uint2* __restrict__ out, int N) {
    int node = (blockIdx.x * 256 + threadIdx.x) >> 5;
    int lane = threadIdx.x & 31;
    if (node >= N) return;
    const char* xb = (const char*)x + ((size_t)lane << 4);
    int i = g_off[node], e = g_off[node + 1];
    ull a00 = 0, a01 = 0, a10 = 0, a11 = 0;
#define ACC(f, wbits, A0, A1)                                       \
    {                                                               \
        float wv = __int_as_float(wbits);                           \
        ull wp = pack2(wv, wv);                                     \
        A0 = ffma2(pack2((f).x, (f).y), wp, A0);                    \
        A1 = ffma2(pack2((f).z, (f).w), wp, A1);                    \
    }
    for (; i + 8 <= e; i += 8) {
        int2 e0 = __ldcs(&g_edge[i]);
        int2 e1 = __ldcs(&g_edge[i + 1]);
        int2 e2 = __ldcs(&g_edge[i + 2]);
        int2 e3 = __ldcs(&g_edge[i + 3]);
        int2 e4 = __ldcs(&g_edge[i + 4]);
        int2 e5 = __ldcs(&g_edge[i + 5]);
        int2 e6 = __ldcs(&g_edge[i + 6]);
        int2 e7 = __ldcs(&g_edge[i + 7]);
        float4 f0 = *(const float4*)(xb + ((size_t)(unsigned)e0.x << 9));
        float4 f1 = *(const float4*)(xb + ((size_t)(unsigned)e1.x << 9));
        float4 f2 = *(const float4*)(xb + ((size_t)(unsigned)e2.x << 9));
        float4 f3 = *(const float4*)(xb + ((size_t)(unsigned)e3.x << 9));
        float4 f4 = *(const float4*)(xb + ((size_t)(unsigned)e4.x << 9));
        float4 f5 = *(const float4*)(xb + ((size_t)(unsigned)e5.x << 9));
        float4 f6 = *(const float4*)(xb + ((size_t)(unsigned)e6.x << 9));
        float4 f7 = *(const float4*)(xb + ((size_t)(unsigned)e7.x << 9));
        ACC(f0, e0.y, a00, a01); ACC(f1, e1.y, a10, a11);
        ACC(f2, e2.y, a00, a01); ACC(f3, e3.y, a10, a11);
        ACC(f4, e4.y, a00, a01); ACC(f5, e5.y, a10, a11);
        ACC(f6, e6.y, a00, a01); ACC(f7, e7.y, a10, a11);
    }
    while (i < e) {
        int m = e - i;
        int2 e0 = __ldcs(&g_edge[i]);
        int2 e1 = __ldcs(&g_edge[i + ((m > 1) ? 1 : 0)]);
        int2 e2 = __ldcs(&g_edge[i + ((m > 2) ? 2 : 0)]);
        int2 e3 = __ldcs(&g_edge[i + ((m > 3) ? 3 : 0)]);
        if (m <= 1) e1.y = 0;
        if (m <= 2) e2.y = 0;
        if (m <= 3) e3.y = 0;
        float4 f0 = *(const float4*)(xb + ((size_t)(unsigned)e0.x << 9));
        float4 f1 = *(const float4*)(xb + ((size_t)(unsigned)e1.x << 9));
        float4 f2 = *(const float4*)(xb + ((size_t)(unsigned)e2.x << 9));
        float4 f3 = *(const float4*)(xb + ((size_t)(unsigned)e3.x << 9));
        ACC(f0, e0.y, a00, a01); ACC(f1, e1.y, a10, a11);
        ACC(f2, e2.y, a00, a01); ACC(f3, e3.y, a10, a11);
        i += 4;
    }
#undef ACC
    float2 ra = unpack2(a00), rb = unpack2(a10);
    float2 ra2 = unpack2(a01), rb2 = unpack2(a11);
    __half2 h01 = __floats2half2_rn(ra.x + rb.x, ra.y + rb.y);
    __half2 h23 = __floats2half2_rn(ra2.x + rb2.x, ra2.y + rb2.y);
    uint2 u;
    u.x = *(uint32_t*)&h01;
    u.y = *(uint32_t*)&h23;
    __stcs(&out[(size_t)node * 32 + lane], u);
}

// ---------------- aggregation (fp16 source, layers 2/3) -> fp16 out --------
__global__ void __launch_bounds__(256)
k_agg_h(const __half* __restrict__ x, uint2* __restrict__ out, int N) {
    int node = (blockIdx.x * 256 + threadIdx.x) >> 5;
    int lane = threadIdx.x & 31;
    if (node >= N) return;
    const char* xb = (const char*)x + ((size_t)lane << 3);
    int i = g_off[node], e = g_off[node + 1];
    ull a00 = 0, a01 = 0, a10 = 0, a11 = 0;
#define ACCH(f, wbits, A0, A1)                                      \
    {                                                               \
        float wv = __int_as_float(wbits);                           \
        ull wp = pack2(wv, wv);                                     \
        float2 p01 = __half22float2(*(const __half2*)&(f).x);       \
        float2 p23 = __half22float2(*(const __half2*)&(f).y);       \
        A0 = ffma2(pack2(p01.x, p01.y), wp, A0);                    \
        A1 = ffma2(pack2(p23.x, p23.y), wp, A1);                    \
    }
    for (; i + 8 <= e; i += 8) {
        int2 e0 = __ldcs(&g_edge[i]);
        int2 e1 = __ldcs(&g_edge[i + 1]);
        int2 e2 = __ldcs(&g_edge[i + 2]);
        int2 e3 = __ldcs(&g_edge[i + 3]);
        int2 e4 = __ldcs(&g_edge[i + 4]);
        int2 e5 = __ldcs(&g_edge[i + 5]);
        int2 e6 = __ldcs(&g_edge[i + 6]);
        int2 e7 = __ldcs(&g_edge[i + 7]);
        uint2 f0 = *(const uint2*)(xb + ((size_t)(unsigned)e0.x << 8));
        uint2 f1 = *(const uint2*)(xb + ((size_t)(unsigned)e1.x << 8));
        uint2 f2 = *(const uint2*)(xb + ((size_t)(unsigned)e2.x << 8));
        uint2 f3 = *(const uint2*)(xb + ((size_t)(unsigned)e3.x << 8));
        uint2 f4 = *(const uint2*)(xb + ((size_t)(unsigned)e4.x << 8));
        uint2 f5 = *(const uint2*)(xb + ((size_t)(unsigned)e5.x << 8));
        uint2 f6 = *(const uint2*)(xb + ((size_t)(unsigned)e6.x << 8));
        uint2 f7 = *(const uint2*)(xb + ((size_t)(unsigned)e7.x << 8));
        ACCH(f0, e0.y, a00, a01); ACCH(f1, e1.y, a10, a11);
        ACCH(f2, e2.y, a00, a01); ACCH(f3, e3.y, a10, a11);
        ACCH(f4, e4.y, a00, a01); ACCH(f5, e5.y, a10, a11);
        ACCH(f6, e6.y, a00, a01); ACCH(f7, e7.y, a10, a11);
    }
    while (i < e) {
        int m = e - i;
        int2 e0 = __ldcs(&g_edge[i]);
        int2 e1 = __ldcs(&g_edge[i + ((m > 1) ? 1 : 0)]);
        int2 e2 = __ldcs(&g_edge[i + ((m > 2) ? 2 : 0)]);
        int2 e3 = __ldcs(&g_edge[i + ((m > 3) ? 3 : 0)]);
        if (m <= 1) e1.y = 0;
        if (m <= 2) e2.y = 0;
        if (m <= 3) e3.y = 0;
        uint2 f0 = *(const uint2*)(xb + ((size_t)(unsigned)e0.x << 8));
        uint2 f1 = *(const uint2*)(xb + ((size_t)(unsigned)e1.x << 8));
        uint2 f2 = *(const uint2*)(xb + ((size_t)(unsigned)e2.x << 8));
        uint2 f3 = *(const uint2*)(xb + ((size_t)(unsigned)e3.x << 8));
        ACCH(f0, e0.y, a00, a01); ACCH(f1, e1.y, a10, a11);
        ACCH(f2, e2.y, a00, a01); ACCH(f3, e3.y, a10, a11);
        i += 4;
    }
#undef ACCH
    float2 ra = unpack2(a00), rb = unpack2(a10);
    float2 ra2 = unpack2(a01), rb2 = unpack2(a11);
    __half2 h01 = __floats2half2_rn(ra.x + rb.x, ra.y + rb.y);
    __half2 h23 = __floats2half2_rn(ra2.x + rb2.x, ra2.y + rb2.y);
    uint2 u;
    u.x = *(uint32_t*)&h01;
    u.y = *(uint32_t*)&h23;
    __stcs(&out[(size_t)node * 32 + lane], u);
}

// ---------------- W prep: fp16 hi + fp16 residual --------------------------
__global__ void k_wprep(const float* __restrict__ W1, const float* __restrict__ W2,
                        const float* __restrict__ W3) {
    int i = blockIdx.x * 256 + threadIdx.x;      // < 24576
    int lane = i & 31, nt = (i >> 5) & 15, s = (i >> 9) & 7;
    int part = (i >> 12) & 1, layer = i >> 13;
    const float* W = (layer == 0) ? W1 : (layer == 1) ? W2 : W3;
    int k0 = (s << 4) + ((lane & 3) << 1);
    int n  = (nt << 3) + (lane >> 2);
    float v00 = __ldg(&W[(k0 << 7) + n]);
    float v01 = __ldg(&W[((k0 + 1) << 7) + n]);
    float v10 = __ldg(&W[((k0 + 8) << 7) + n]);
    float v11 = __ldg(&W[((k0 + 9) << 7) + n]);
    __half2 b0, b1;
    if (part == 0) {
        b0.x = __float2half_rn(v00); b0.y = __float2half_rn(v01);
        b1.x = __float2half_rn(v10); b1.y = __float2half_rn(v11);
    } else {
        __half h;
        h = __float2half_rn(v00); b0.x = __float2half_rn(v00 - __half2float(h));
        h = __float2half_rn(v01); b0.y = __float2half_rn(v01 - __half2float(h));
        h = __float2half_rn(v10); b1.x = __float2half_rn(v10 - __half2float(h));
        h = __float2half_rn(v11); b1.y = __float2half_rn(v11 - __half2float(h));
    }
    uint2 pk;
    pk.x = *(uint32_t*)&b0;
    pk.y = *(uint32_t*)&b1;
    g_wpk[i] = *(ull*)&pk;
}

// ---------------- persistent HMMA GEMM (fp16 A) + fused stats --------------
// grid = min(ntiles,296). smem: A[64x272]=17408, Wh+Wl=65536, red=1024 -> 83968
#define A_STRIDE 272
#define SMA 0
#define SMW 17408
#define SM_RED 82944
#define SM_TOT 83968
#define GEMM_GRID 296

__global__ void __launch_bounds__(256, 2)
k_gemm_mma(const __half* __restrict__ A, const ull* __restrict__ Wpk,
           const float* __restrict__ bias, float* __restrict__ out,
           float* __restrict__ stat_part, int N, int ntiles) {
    extern __shared__ char smem[];
    uint32_t sb = smem_u32(smem);
    float* red = (float*)(smem + SM_RED);
    int t = threadIdx.x, lane = t & 31, w = t >> 5;

    // stage W once (64KB raw copy)
    {
        const int4* src = (const int4*)Wpk;
        int4* dst = (int4*)(smem + SMW);
        for (int i = t; i < 4096; i += 256) dst[i] = src[i];
    }
    if (stat_part && t < 256) red[t] = 0.0f;

    int sub = w & 3, ch = w >> 2;
    uint32_t arow = (uint32_t)((16 * sub + (lane & 7) + ((lane >> 3) & 1) * 8) * A_STRIDE +
                               ((lane >> 4) << 4));
    int c0 = (ch << 6) + ((lane & 3) << 1);
    float bb0 = 0.f, bb1 = 0.f;

    for (int tile = blockIdx.x; tile < ntiles; tile += GEMM_GRID) {
        int row0 = tile << 6;
        // stage A (raw fp16 copy, zero-pad tail rows)
#pragma unroll
        for (int j = 0; j < 4; j++) {
            int i = t + 256 * j;
            int r = i >> 4, chk = i & 15;
            uint4 v = make_uint4(0u, 0u, 0u, 0u);
            if (row0 + r < N)
                v = __ldcs((const uint4*)(A + (size_t)(row0 + r) * 128 + (chk << 3)));
            *(uint4*)(smem + SMA + r * A_STRIDE + (chk << 4)) = v;
        }
        __syncthreads();

        float acc[8][4];
#pragma unroll
        for (int nt = 0; nt < 8; nt++)
#pragma unroll
            for (int c = 0; c < 4; c++) acc[nt][c] = 0.0f;

        uint32_t abase = sb + SMA + arow;
#pragma unroll
        for (int pass = 0; pass < 2; pass++) {
            uint32_t wbase = sb + SMW + ((pass == 1) ? 32768u : 0u) + (lane << 3) +
                             ((uint32_t)ch << 11);
            for (int s = 0; s < 8; s++) {
                uint32_t a0, a1, a2, a3;
                asm volatile(
                    "ldmatrix.sync.aligned.m8n8.x4.shared.b16 {%0,%1,%2,%3}, [%4];"
                    : "=r"(a0), "=r"(a1), "=r"(a2), "=r"(a3)
                    : "r"(abase + (s << 5)));
                uint32_t wrow = wbase + (s << 12);
#pragma unroll
                for (int nt = 0; nt < 8; nt++) {
                    uint32_t b0, b1;
                    asm volatile("ld.shared.v2.u32 {%0,%1}, [%2];"
                                 : "=r"(b0), "=r"(b1) : "r"(wrow + (nt << 8)));
                    asm volatile(
                        "mma.sync.aligned.m16n8k16.row.col.f32.f16.f16.f32 "
                        "{%0,%1,%2,%3}, {%4,%5,%6,%7}, {%8,%9}, {%0,%1,%2,%3};"
                        : "+f"(acc[nt][0]), "+f"(acc[nt][1]),
                          "+f"(acc[nt][2]), "+f"(acc[nt][3])
                        : "r"(a0), "r"(a1), "r"(a2), "r"(a3), "r"(b0), "r"(b1));
                }
            }
        }
        __syncthreads();

        // epilogue: output write
        int gr = (tile << 6) + 16 * sub + (lane >> 2);
        bool val0 = gr < N, val1 = (gr + 8) < N;
        float* o0 = out + (size_t)gr * 128;
        float* o1 = o0 + 8 * 128;
#pragma unroll
        for (int nt = 0; nt < 8; nt++) {
            int col = (nt << 3) + c0;
            if (bias) { bb0 = __ldg(&bias[col]); bb1 = __ldg(&bias[col + 1]); }
            if (val0) *(float2*)(o0 + col) = make_float2(acc[nt][0] + bb0, acc[nt][1] + bb1);
            if (val1) *(float2*)(o1 + col) = make_float2(acc[nt][2] + bb0, acc[nt][3] + bb1);
        }
        // fused stats: row-reduce in regs, shfl over 8 row-lanes, lanes<4 -> smem
        if (stat_part) {
            float ts[16], tq[16];
#pragma unroll
            for (int nt = 0; nt < 8; nt++) {
                ts[2 * nt]     = acc[nt][0] + acc[nt][2];
                ts[2 * nt + 1] = acc[nt][1] + acc[nt][3];
                tq[2 * nt]     = fmaf(acc[nt][0], acc[nt][0], acc[nt][2] * acc[nt][2]);
                tq[2 * nt + 1] = fmaf(acc[nt][1], acc[nt][1], acc[nt][3] * acc[nt][3]);
            }
#pragma unroll
            for (int q = 0; q < 16; q++) {
#pragma unroll
                for (int msk = 4; msk <= 16; msk <<= 1) {
                    ts[q] += __shfl_xor_sync(0xffffffffu, ts[q], msk);
                    tq[q] += __shfl_xor_sync(0xffffffffu, tq[q], msk);
                }
            }
            if (lane < 4) {
#pragma unroll
                for (int q = 0; q < 16; q++) {
                    int col = ((q >> 1) << 3) + c0 + (q & 1);
                    atomicAdd(&red[col], ts[q]);
                    atomicAdd(&red[128 + col], tq[q]);
                }
            }
        }
    }
    if (stat_part) {
        __syncthreads();
        if (t < 256) stat_part[blockIdx.x * 256 + t] = red[t];
    }
}

// ---------------- bnfin: reduce gemm-block partials ------------------------
__global__ void k_bnfin(const float* __restrict__ part, int nblk,
                        const float* __restrict__ gamma, const float* __restrict__ beta,
                        float* __restrict__ scale, float* __restrict__ shift, float invN) {
    int t = threadIdx.x;  // 128
    float sm = 0.f, sq = 0.f;
    for (int b = 0; b < nblk; b++) {
        sm += part[b * 256 + t];
        sq += part[b * 256 + 128 + t];
    }
    float m = sm * invN;
    float v = fmaf(-m, m, sq * invN);
    float s = gamma[t] * rsqrtf(v + 1e-5f);
    scale[t] = s;
    shift[t] = fmaf(-m, s, beta[t]);
}

// ---------------- bnpoly: fp32 in, BN+poly, fp16 out -----------------------
__global__ void k_bnpoly_h(const float* __restrict__ X, __half* __restrict__ H,
                           const float* __restrict__ scale, const float* __restrict__ shift,
                           const float* __restrict__ co, int N) {
    int i = blockIdx.x * 256 + threadIdx.x;
    if (i >= N * 32) return;
    int c4 = i & 31;
    float4 sc = *(const float4*)&scale[c4 << 2];
    float4 sh = *(const float4*)&shift[c4 << 2];
    float c0 = __ldg(&co[0]), c1 = __ldg(&co[1]), c2 = __ldg(&co[2]);
    float c3 = __ldg(&co[3]), cl = __ldg(&co[4]);
    float4 v = __ldcs(&((const float4*)X)[i]);
    float x, p;
    x = fmaf(v.x, sc.x, sh.x);
    p = fmaf(cl, x, c3); p = fmaf(p, x, c2); p = fmaf(p, x, c1); v.x = fmaf(p, x, c0);
    x = fmaf(v.y, sc.y, sh.y);
    p = fmaf(cl, x, c3); p = fmaf(p, x, c2); p = fmaf(p, x, c1); v.y = fmaf(p, x, c0);
    x = fmaf(v.z, sc.z, sh.z);
    p = fmaf(cl, x, c3); p = fmaf(p, x, c2); p = fmaf(p, x, c1); v.z = fmaf(p, x, c0);
    x = fmaf(v.w, sc.w, sh.w);
    p = fmaf(cl, x, c3); p = fmaf(p, x, c2); p = fmaf(p, x, c1); v.w = fmaf(p, x, c0);
    __half2 h01 = __floats2half2_rn(v.x, v.y);
    __half2 h23 = __floats2half2_rn(v.z, v.w);
    uint2 u;
    u.x = *(uint32_t*)&h01;
    u.y = *(uint32_t*)&h23;
    ((uint2*)H)[i] = u;
}

// ---------------------------------------------------------------------------
extern "C" void kernel_launch(void* const* d_in, const int* in_sizes, int n_in,
                              void* d_out, int out_size) {
    const float* nf     = (const float*)d_in[0];
    const int*   row    = (const int*)  d_in[1];
    const int*   col    = (const int*)  d_in[2];
    const float* ew     = (const float*)d_in[3];
    const float* W1     = (const float*)d_in[4];
    const float* W2     = (const float*)d_in[6];
    const float* W3     = (const float*)d_in[8];
    const float* b3     = (const float*)d_in[9];
    const float* gamma1 = (const float*)d_in[10];
    const float* beta1  = (const float*)d_in[11];
    const float* gamma2 = (const float*)d_in[12];
    const float* beta2  = (const float*)d_in[13];
    const float* coeffs = (const float*)d_in[14];
    float* out = (float*)d_out;

    int N = in_sizes[0] / 128;
    int E = in_sizes[1];

    cudaFuncSetAttribute(k_gemm_mma, cudaFuncAttributeMaxDynamicSharedMemorySize, SM_TOT);

    void* p;
    cudaGetSymbolAddress(&p, g_bufB);  float*  bufB  = (float*)p;
    cudaGetSymbolAddress(&p, g_hbufA); __half* hbufA = (__half*)p;
    cudaGetSymbolAddress(&p, g_hbuf);  __half* hbuf  = (__half*)p;
    cudaGetSymbolAddress(&p, g_wpk);   ull*    wpk   = (ull*)p;
    cudaGetSymbolAddress(&p, g_part);  float*  part  = (float*)p;
    cudaGetSymbolAddress(&p, g_scale); float*  scale = (float*)p;
    cudaGetSymbolAddress(&p, g_shift); float*  shift = (float*)p;

    int nb  = (N + 1023) / 1024;
    int eb4 = (E + 1023) / 1024;
    int ab  = (N + 7) / 8;
    int ntiles = (N + 63) / 64;
    int gg = (ntiles < GEMM_GRID) ? ntiles : GEMM_GRID;
    int tb = (N * 32 + 255) / 256;
    float invN = 1.0f / (float)N;

    // CSR build (k_agg = global launch index 3 for ncu)
    k_count<<<eb4, 256>>>(row, E);
    k_scan <<<nb, 256>>>(nb, N);
    k_fill <<<eb4, 256>>>(row, col, ew, E);

    // Layer 1 (b1 cancels in BN)
    k_agg     <<<ab, 256>>>(nf, (uint2*)hbufA, N);
    k_wprep   <<<96, 256>>>(W1, W2, W3);
    k_gemm_mma<<<gg, 256, SM_TOT>>>(hbufA, wpk, nullptr, bufB, part, N, ntiles);
    k_bnfin   <<<1, 128>>>(part, gg, gamma1, beta1, scale, shift, invN);
    k_bnpoly_h<<<tb, 256>>>(bufB, hbuf, scale, shift, coeffs, N);

    // Layer 2 (b2 cancels)
    k_agg_h   <<<ab, 256>>>(hbuf, (uint2*)hbufA, N);
    k_gemm_mma<<<gg, 256, SM_TOT>>>(hbufA, wpk + 8192, nullptr, bufB, part, N, ntiles);
    k_bnfin   <<<1, 128>>>(part, gg, gamma2, beta2, scale, shift, invN);
    k_bnpoly_h<<<tb, 256>>>(bufB, hbuf, scale, shift, coeffs + 5, N);

    // Layer 3 (bias b3 kept) -> d_out
    k_agg_h   <<<ab, 256>>>(hbuf, (uint2*)hbufA, N);
    k_gemm_mma<<<gg, 256, SM_TOT>>>(hbufA, wpk + 16384, b3, out, nullptr, N, ntiles);
}

// round 16
// speedup vs baseline: 1.0303x; 1.0303x over previous
#include <cuda_runtime.h>
#include <cuda_fp16.h>
#include <cstdint>

// ---------------------------------------------------------------------------
// PolyActGCN: CSR build (vec4) -> agg(->fp16) -> GEMM(fp16 A, W hi+lo, 2-pass
// HMMA) -> stats -> bnfin -> bnpoly(->fp16) -> agg_h -> ... -> GEMM(+b3) -> out
// GEMM persistent-CTA (296 blocks, W staged once). All activations fp16.
// ---------------------------------------------------------------------------

#define NMAX 131072
#define EMAX 2097152
typedef unsigned long long ull;

__device__ float  g_bufB[(size_t)NMAX * 128];    // fp32 GEMM output
__device__ __half g_hbufA[(size_t)NMAX * 128];   // fp16 agg output (GEMM A)
__device__ __half g_hbuf[(size_t)NMAX * 128];    // fp16 activations
__device__ int    g_deg[NMAX];           // invariant: zero at launch entry
__device__ int    g_cur[NMAX];
__device__ int    g_off[NMAX + 1];
__device__ int2   g_edge[EMAX];
__device__ ull    g_epoch;
__device__ ull    g_pub[128];
__device__ ull    g_wpk[3 * 8192];       // [layer][part][s][nt][lane] fp16x4
__device__ float  g_stats[512];          // invariant: zero at launch entry
__device__ float  g_scale[128];
__device__ float  g_shift[128];

// ---------------- helpers --------------------------------------------------
static __device__ __forceinline__ ull pack2(float x, float y) {
    ull p;
    asm("mov.b64 %0, {%1, %2};" : "=l"(p)
        : "r"(__float_as_uint(x)), "r"(__float_as_uint(y)));
    return p;
}
static __device__ __forceinline__ float2 unpack2(ull p) {
    unsigned int a, b;
    asm("mov.b64 {%0, %1}, %2;" : "=r"(a), "=r"(b) : "l"(p));
    return make_float2(__uint_as_float(a), __uint_as_float(b));
}
static __device__ __forceinline__ ull ffma2(ull a, ull b, ull c) {
    ull d;
    asm("fma.rn.f32x2 %0, %1, %2, %3;" : "=l"(d) : "l"(a), "l"(b), "l"(c));
    return d;
}
static __device__ __forceinline__ uint32_t smem_u32(const void* p) {
    uint32_t a;
    asm("{ .reg .u64 t; cvta.to.shared.u64 t, %1; cvt.u32.u64 %0, t; }"
        : "=r"(a) : "l"(p));
    return a;
}

// ---------------- CSR build (4 edges / thread) -----------------------------
__global__ void k_count(const int* __restrict__ row, int E) {
    if (blockIdx.x == 0 && threadIdx.x == 0) atomicAdd(&g_epoch, 1ULL);
    int i = (blockIdx.x * 256 + threadIdx.x) << 2;
    if (i + 4 <= E) {
        int4 r = __ldcs((const int4*)&row[i]);
        atomicAdd(&g_deg[r.x], 1);
        atomicAdd(&g_deg[r.y], 1);
        atomicAdd(&g_deg[r.z], 1);
        atomicAdd(&g_deg[r.w], 1);
    } else {
        for (; i < E; i++) atomicAdd(&g_deg[__ldcs(&row[i])], 1);
    }
}

__global__ void k_scan(int nb, int N) {
    __shared__ int sh[256];
    __shared__ int bsum[128];
    int b = blockIdx.x, t = threadIdx.x;
    ull epoch = g_epoch;
    int idx = (b << 8) + t;
    int4 d4 = ((const int4*)g_deg)[idx];
    ((int4*)g_deg)[idx] = make_int4(0, 0, 0, 0);
    int s0 = d4.x, s1 = s0 + d4.y, s2 = s1 + d4.z, s3 = s2 + d4.w;
    sh[t] = s3;
    __syncthreads();
    for (int d = 1; d < 256; d <<= 1) {
        int u = (t >= d) ? sh[t - d] : 0;
        __syncthreads();
        sh[t] += u;
        __syncthreads();
    }
    if (t == 0) atomicExch(&g_pub[b], (epoch << 32) | (unsigned)sh[255]);
    if (t < nb) {
        ull v;
        do { v = *(volatile ull*)&g_pub[t]; } while ((v >> 32) != (epoch & 0xffffffffULL));
        bsum[t] = (int)(v & 0xffffffffULL);
    }
    __syncthreads();
    int pre = 0;
    for (int j = 0; j < b; j++) pre += bsum[j];
    if (b == 0 && t == 0) {
        int tot = 0;
        for (int j = 0; j < nb; j++) tot += bsum[j];
        g_off[N] = tot;
    }
    int pr = pre + sh[t] - s3;
    int4 o4 = make_int4(pr, pr + s0, pr + s1, pr + s2);
    ((int4*)g_off)[idx] = o4;
    ((int4*)g_cur)[idx] = o4;
}

__global__ void k_fill(const int* __restrict__ row, const int* __restrict__ col,
                       const float* __restrict__ ew, int E) {
    int i = (blockIdx.x * 256 + threadIdx.x) << 2;
    if (i + 4 <= E) {
        int4 r = __ldcs((const int4*)&row[i]);
        int4 c = __ldcs((const int4*)&col[i]);
        float4 w = __ldcs((const float4*)&ew[i]);
        int p0 = atomicAdd(&g_cur[r.x], 1);
        int p1 = atomicAdd(&g_cur[r.y], 1);
        int p2 = atomicAdd(&g_cur[r.z], 1);
        int p3 = atomicAdd(&g_cur[r.w], 1);
        g_edge[p0] = make_int2(c.x, __float_as_int(w.x));
        g_edge[p1] = make_int2(c.y, __float_as_int(w.y));
        g_edge[p2] = make_int2(c.z, __float_as_int(w.z));
        g_edge[p3] = make_int2(c.w, __float_as_int(w.w));
    } else {
        for (; i < E; i++) {
            int p = atomicAdd(&g_cur[__ldcs(&row[i])], 1);
            g_edge[p] = make_int2(__ldcs(&col[i]), __float_as_int(__ldcs(&ew[i])));
        }
    }
}

// ---------------- aggregation (fp32 source, layer 1) -> fp16 out -----------
__global__ void __launch_bounds__(256)
k_agg(const float* __restrict__ x, uint2* __restrict__ out, int N) {
    int node = (blockIdx.x * 256 + threadIdx.x) >> 5;
    int lane = threadIdx.x & 31;
    if (node >= N) return;
    const char* xb = (const char*)x + ((size_t)lane << 4);
    int i = g_off[node], e = g_off[node + 1];
    ull a00 = 0, a01 = 0, a10 = 0, a11 = 0;
#define ACC(f, wbits, A0, A1)                                       \
    {                                                               \
        float wv = __int_as_float(wbits);                           \
        ull wp = pack2(wv, wv);                                     \
        A0 = ffma2(pack2((f).x, (f).y), wp, A0);                    \
        A1 = ffma2(pack2((f).z, (f).w), wp, A1);                    \
    }
    for (; i + 8 <= e; i += 8) {
        int2 e0 = __ldcs(&g_edge[i]);
        int2 e1 = __ldcs(&g_edge[i + 1]);
        int2 e2 = __ldcs(&g_edge[i + 2]);
        int2 e3 = __ldcs(&g_edge[i + 3]);
        int2 e4 = __ldcs(&g_edge[i + 4]);
        int2 e5 = __ldcs(&g_edge[i + 5]);
        int2 e6 = __ldcs(&g_edge[i + 6]);
        int2 e7 = __ldcs(&g_edge[i + 7]);
        float4 f0 = *(const float4*)(xb + ((size_t)(unsigned)e0.x << 9));
        float4 f1 = *(const float4*)(xb + ((size_t)(unsigned)e1.x << 9));
        float4 f2 = *(const float4*)(xb + ((size_t)(unsigned)e2.x << 9));
        float4 f3 = *(const float4*)(xb + ((size_t)(unsigned)e3.x << 9));
        float4 f4 = *(const float4*)(xb + ((size_t)(unsigned)e4.x << 9));
        float4 f5 = *(const float4*)(xb + ((size_t)(unsigned)e5.x << 9));
        float4 f6 = *(const float4*)(xb + ((size_t)(unsigned)e6.x << 9));
        float4 f7 = *(const float4*)(xb + ((size_t)(unsigned)e7.x << 9));
        ACC(f0, e0.y, a00, a01); ACC(f1, e1.y, a10, a11);
        ACC(f2, e2.y, a00, a01); ACC(f3, e3.y, a10, a11);
        ACC(f4, e4.y, a00, a01); ACC(f5, e5.y, a10, a11);
        ACC(f6, e6.y, a00, a01); ACC(f7, e7.y, a10, a11);
    }
    while (i < e) {
        int m = e - i;
        int2 e0 = __ldcs(&g_edge[i]);
        int2 e1 = __ldcs(&g_edge[i + ((m > 1) ? 1 : 0)]);
        int2 e2 = __ldcs(&g_edge[i + ((m > 2) ? 2 : 0)]);
        int2 e3 = __ldcs(&g_edge[i + ((m > 3) ? 3 : 0)]);
        if (m <= 1) e1.y = 0;
        if (m <= 2) e2.y = 0;
        if (m <= 3) e3.y = 0;
        float4 f0 = *(const float4*)(xb + ((size_t)(unsigned)e0.x << 9));
        float4 f1 = *(const float4*)(xb + ((size_t)(unsigned)e1.x << 9));
        float4 f2 = *(const float4*)(xb + ((size_t)(unsigned)e2.x << 9));
        float4 f3 = *(const float4*)(xb + ((size_t)(unsigned)e3.x << 9));
        ACC(f0, e0.y, a00, a01); ACC(f1, e1.y, a10, a11);
        ACC(f2, e2.y, a00, a01); ACC(f3, e3.y, a10, a11);
        i += 4;
    }
#undef ACC
    float2 ra = unpack2(a00), rb = unpack2(a10);
    float2 ra2 = unpack2(a01), rb2 = unpack2(a11);
    __half2 h01 = __floats2half2_rn(ra.x + rb.x, ra.y + rb.y);
    __half2 h23 = __floats2half2_rn(ra2.x + rb2.x, ra2.y + rb2.y);
    uint2 u;
    u.x = *(uint32_t*)&h01;
    u.y = *(uint32_t*)&h23;
    __stcs(&out[(size_t)node * 32 + lane], u);
}

// ---------------- aggregation (fp16 source, layers 2/3) -> fp16 out --------
__global__ void __launch_bounds__(256)
k_agg_h(const __half* __restrict__ x, uint2* __restrict__ out, int N) {
    int node = (blockIdx.x * 256 + threadIdx.x) >> 5;
    int lane = threadIdx.x & 31;
    if (node >= N) return;
    const char* xb = (const char*)x + ((size_t)lane << 3);
    int i = g_off[node], e = g_off[node + 1];
    ull a00 = 0, a01 = 0, a10 = 0, a11 = 0;
#define ACCH(f, wbits, A0, A1)                                      \
    {                                                               \
        float wv = __int_as_float(wbits);                           \
        ull wp = pack2(wv, wv);                                     \
        float2 p01 = __half22float2(*(const __half2*)&(f).x);       \
        float2 p23 = __half22float2(*(const __half2*)&(f).y);       \
        A0 = ffma2(pack2(p01.x, p01.y), wp, A0);                    \
        A1 = ffma2(pack2(p23.x, p23.y), wp, A1);                    \
    }
    for (; i + 8 <= e; i += 8) {
        int2 e0 = __ldcs(&g_edge[i]);
        int2 e1 = __ldcs(&g_edge[i + 1]);
        int2 e2 = __ldcs(&g_edge[i + 2]);
        int2 e3 = __ldcs(&g_edge[i + 3]);
        int2 e4 = __ldcs(&g_edge[i + 4]);
        int2 e5 = __ldcs(&g_edge[i + 5]);
        int2 e6 = __ldcs(&g_edge[i + 6]);
        int2 e7 = __ldcs(&g_edge[i + 7]);
        uint2 f0 = *(const uint2*)(xb + ((size_t)(unsigned)e0.x << 8));
        uint2 f1 = *(const uint2*)(xb + ((size_t)(unsigned)e1.x << 8));
        uint2 f2 = *(const uint2*)(xb + ((size_t)(unsigned)e2.x << 8));
        uint2 f3 = *(const uint2*)(xb + ((size_t)(unsigned)e3.x << 8));
        uint2 f4 = *(const uint2*)(xb + ((size_t)(unsigned)e4.x << 8));
        uint2 f5 = *(const uint2*)(xb + ((size_t)(unsigned)e5.x << 8));
        uint2 f6 = *(const uint2*)(xb + ((size_t)(unsigned)e6.x << 8));
        uint2 f7 = *(const uint2*)(xb + ((size_t)(unsigned)e7.x << 8));
        ACCH(f0, e0.y, a00, a01); ACCH(f1, e1.y, a10, a11);
        ACCH(f2, e2.y, a00, a01); ACCH(f3, e3.y, a10, a11);
        ACCH(f4, e4.y, a00, a01); ACCH(f5, e5.y, a10, a11);
        ACCH(f6, e6.y, a00, a01); ACCH(f7, e7.y, a10, a11);
    }
    while (i < e) {
        int m = e - i;
        int2 e0 = __ldcs(&g_edge[i]);
        int2 e1 = __ldcs(&g_edge[i + ((m > 1) ? 1 : 0)]);
        int2 e2 = __ldcs(&g_edge[i + ((m > 2) ? 2 : 0)]);
        int2 e3 = __ldcs(&g_edge[i + ((m > 3) ? 3 : 0)]);
        if (m <= 1) e1.y = 0;
        if (m <= 2) e2.y = 0;
        if (m <= 3) e3.y = 0;
        uint2 f0 = *(const uint2*)(xb + ((size_t)(unsigned)e0.x << 8));
        uint2 f1 = *(const uint2*)(xb + ((size_t)(unsigned)e1.x << 8));
        uint2 f2 = *(const uint2*)(xb + ((size_t)(unsigned)e2.x << 8));
        uint2 f3 = *(const uint2*)(xb + ((size_t)(unsigned)e3.x << 8));
        ACCH(f0, e0.y, a00, a01); ACCH(f1, e1.y, a10, a11);
        ACCH(f2, e2.y, a00, a01); ACCH(f3, e3.y, a10, a11);
        i += 4;
    }
#undef ACCH
    float2 ra = unpack2(a00), rb = unpack2(a10);
    float2 ra2 = unpack2(a01), rb2 = unpack2(a11);
    __half2 h01 = __floats2half2_rn(ra.x + rb.x, ra.y + rb.y);
    __half2 h23 = __floats2half2_rn(ra2.x + rb2.x, ra2.y + rb2.y);
    uint2 u;
    u.x = *(uint32_t*)&h01;
    u.y = *(uint32_t*)&h23;
    __stcs(&out[(size_t)node * 32 + lane], u);
}

// ---------------- W prep: fp16 hi + fp16 residual --------------------------
__global__ void k_wprep(const float* __restrict__ W1, const float* __restrict__ W2,
                        const float* __restrict__ W3) {
    int i = blockIdx.x * 256 + threadIdx.x;      // < 24576
    int lane = i & 31, nt = (i >> 5) & 15, s = (i >> 9) & 7;
    int part = (i >> 12) & 1, layer = i >> 13;
    const float* W = (layer == 0) ? W1 : (layer == 1) ? W2 : W3;
    int k0 = (s << 4) + ((lane & 3) << 1);
    int n  = (nt << 3) + (lane >> 2);
    float v00 = __ldg(&W[(k0 << 7) + n]);
    float v01 = __ldg(&W[((k0 + 1) << 7) + n]);
    float v10 = __ldg(&W[((k0 + 8) << 7) + n]);
    float v11 = __ldg(&W[((k0 + 9) << 7) + n]);
    __half2 b0, b1;
    if (part == 0) {
        b0.x = __float2half_rn(v00); b0.y = __float2half_rn(v01);
        b1.x = __float2half_rn(v10); b1.y = __float2half_rn(v11);
    } else {
        __half h;
        h = __float2half_rn(v00); b0.x = __float2half_rn(v00 - __half2float(h));
        h = __float2half_rn(v01); b0.y = __float2half_rn(v01 - __half2float(h));
        h = __float2half_rn(v10); b1.x = __float2half_rn(v10 - __half2float(h));
        h = __float2half_rn(v11); b1.y = __float2half_rn(v11 - __half2float(h));
    }
    uint2 pk;
    pk.x = *(uint32_t*)&b0;
    pk.y = *(uint32_t*)&b1;
    g_wpk[i] = *(ull*)&pk;
}

// ---------------- persistent HMMA GEMM (fp16 A): out = A @ W (+bias) -------
// grid = min(ntiles,296). smem: A[64x272B]=17408, Wh=32768, Wl=32768 -> 82944B
#define A_STRIDE 272
#define SMA 0
#define SMW 17408
#define SM_TOT 82944
#define GEMM_GRID 296

__global__ void __launch_bounds__(256, 2)
k_gemm_mma(const __half* __restrict__ A, const ull* __restrict__ Wpk,
           const float* __restrict__ bias, float* __restrict__ out,
           int N, int ntiles) {
    extern __shared__ char smem[];
    uint32_t sb = smem_u32(smem);
    int t = threadIdx.x, lane = t & 31, w = t >> 5;

    // stage W once (Wh then Wl contiguous: 64KB raw copy)
    {
        const int4* src = (const int4*)Wpk;
        int4* dst = (int4*)(smem + SMW);
        for (int i = t; i < 4096; i += 256) dst[i] = src[i];
    }

    int sub = w & 3, ch = w >> 2;
    uint32_t arow = (uint32_t)((16 * sub + (lane & 7) + ((lane >> 3) & 1) * 8) * A_STRIDE +
                               ((lane >> 4) << 4));
    int c0 = (ch << 6) + ((lane & 3) << 1);
    float bb0 = 0.f, bb1 = 0.f;

    for (int tile = blockIdx.x; tile < ntiles; tile += GEMM_GRID) {
        int row0 = tile << 6;
        // stage A: 64 rows x 16 chunks of 16B (raw fp16 copy, zero-pad tail)
#pragma unroll
        for (int j = 0; j < 4; j++) {
            int i = t + 256 * j;
            int r = i >> 4, chk = i & 15;
            uint4 v = make_uint4(0u, 0u, 0u, 0u);
            if (row0 + r < N)
                v = __ldcs((const uint4*)(A + (size_t)(row0 + r) * 128 + (chk << 3)));
            *(uint4*)(smem + SMA + r * A_STRIDE + (chk << 4)) = v;
        }
        __syncthreads();

        float acc[8][4];
#pragma unroll
        for (int nt = 0; nt < 8; nt++)
#pragma unroll
            for (int c = 0; c < 4; c++) acc[nt][c] = 0.0f;

        uint32_t abase = sb + SMA + arow;
#pragma unroll
        for (int pass = 0; pass < 2; pass++) {
            uint32_t wbase = sb + SMW + ((pass == 1) ? 32768u : 0u) + (lane << 3) +
                             ((uint32_t)ch << 11);
            for (int s = 0; s < 8; s++) {
                uint32_t a0, a1, a2, a3;
                asm volatile(
                    "ldmatrix.sync.aligned.m8n8.x4.shared.b16 {%0,%1,%2,%3}, [%4];"
                    : "=r"(a0), "=r"(a1), "=r"(a2), "=r"(a3)
                    : "r"(abase + (s << 5)));
                uint32_t wrow = wbase + (s << 12);
#pragma unroll
                for (int nt = 0; nt < 8; nt++) {
                    uint32_t b0, b1;
                    asm volatile("ld.shared.v2.u32 {%0,%1}, [%2];"
                                 : "=r"(b0), "=r"(b1) : "r"(wrow + (nt << 8)));
                    asm volatile(
                        "mma.sync.aligned.m16n8k16.row.col.f32.f16.f16.f32 "
                        "{%0,%1,%2,%3}, {%4,%5,%6,%7}, {%8,%9}, {%0,%1,%2,%3};"
                        : "+f"(acc[nt][0]), "+f"(acc[nt][1]),
                          "+f"(acc[nt][2]), "+f"(acc[nt][3])
                        : "r"(a0), "r"(a1), "r"(a2), "r"(a3), "r"(b0), "r"(b1));
                }
            }
        }
        __syncthreads();

        // epilogue
        int gr = (tile << 6) + 16 * sub + (lane >> 2);
        bool val0 = gr < N, val1 = (gr + 8) < N;
        float* o0 = out + (size_t)gr * 128;
        float* o1 = o0 + 8 * 128;
#pragma unroll
        for (int nt = 0; nt < 8; nt++) {
            int col = (nt << 3) + c0;
            if (bias) { bb0 = __ldg(&bias[col]); bb1 = __ldg(&bias[col + 1]); }
            if (val0) *(float2*)(o0 + col) = make_float2(acc[nt][0] + bb0, acc[nt][1] + bb1);
            if (val1) *(float2*)(o1 + col) = make_float2(acc[nt][2] + bb0, acc[nt][3] + bb1);
        }
    }
}

// ---------------- stats / bnfin / bnpoly(->fp16) ---------------------------
__global__ void k_stats(const float* __restrict__ X, float* __restrict__ sum,
                        float* __restrict__ sumsq, int N) {
    __shared__ float s1[256], s2[256];
    int t = threadIdx.x;
    size_t total = (size_t)N * 128;
    float a = 0.f, b = 0.f;
    for (size_t i = (size_t)blockIdx.x * 256 + t; i < total;
         i += (size_t)gridDim.x * 256) {
        float v = X[i];
        a += v;
        b = fmaf(v, v, b);
    }
    s1[t] = a; s2[t] = b;
    __syncthreads();
    if (t < 128) {
        atomicAdd(&sum[t],   s1[t] + s1[t + 128]);
        atomicAdd(&sumsq[t], s2[t] + s2[t + 128]);
    }
}

__global__ void k_bnfin(float* __restrict__ sum, float* __restrict__ sumsq,
                        const float* __restrict__ gamma, const float* __restrict__ beta,
                        float* __restrict__ scale, float* __restrict__ shift, float invN) {
    int t = threadIdx.x;  // 128
    float sm = sum[t], sq = sumsq[t];
    sum[t] = 0.0f;
    sumsq[t] = 0.0f;
    float m = sm * invN;
    float v = fmaf(-m, m, sq * invN);
    float s = gamma[t] * rsqrtf(v + 1e-5f);
    scale[t] = s;
    shift[t] = fmaf(-m, s, beta[t]);
}

__global__ void k_bnpoly_h(const float* __restrict__ X, __half* __restrict__ H,
                           const float* __restrict__ scale, const float* __restrict__ shift,
                           const float* __restrict__ co, int N) {
    int i = blockIdx.x * 256 + threadIdx.x;
    if (i >= N * 32) return;
    int c4 = i & 31;
    float4 sc = *(const float4*)&scale[c4 << 2];
    float4 sh = *(const float4*)&shift[c4 << 2];
    float c0 = __ldg(&co[0]), c1 = __ldg(&co[1]), c2 = __ldg(&co[2]);
    float c3 = __ldg(&co[3]), cl = __ldg(&co[4]);
    float4 v = __ldcs(&((const float4*)X)[i]);
    float x, p;
    x = fmaf(v.x, sc.x, sh.x);
    p = fmaf(cl, x, c3); p = fmaf(p, x, c2); p = fmaf(p, x, c1); v.x = fmaf(p, x, c0);
    x = fmaf(v.y, sc.y, sh.y);
    p = fmaf(cl, x, c3); p = fmaf(p, x, c2); p = fmaf(p, x, c1); v.y = fmaf(p, x, c0);
    x = fmaf(v.z, sc.z, sh.z);
    p = fmaf(cl, x, c3); p = fmaf(p, x, c2); p = fmaf(p, x, c1); v.z = fmaf(p, x, c0);
    x = fmaf(v.w, sc.w, sh.w);
    p = fmaf(cl, x, c3); p = fmaf(p, x, c2); p = fmaf(p, x, c1); v.w = fmaf(p, x, c0);
    __half2 h01 = __floats2half2_rn(v.x, v.y);
    __half2 h23 = __floats2half2_rn(v.z, v.w);
    uint2 u;
    u.x = *(uint32_t*)&h01;
    u.y = *(uint32_t*)&h23;
    ((uint2*)H)[i] = u;
}

// ---------------------------------------------------------------------------
extern "C" void kernel_launch(void* const* d_in, const int* in_sizes, int n_in,
                              void* d_out, int out_size) {
    const float* nf     = (const float*)d_in[0];
    const int*   row    = (const int*)  d_in[1];
    const int*   col    = (const int*)  d_in[2];
    const float* ew     = (const float*)d_in[3];
    const float* W1     = (const float*)d_in[4];
    const float* W2     = (const float*)d_in[6];
    const float* W3     = (const float*)d_in[8];
    const float* b3     = (const float*)d_in[9];
    const float* gamma1 = (const float*)d_in[10];
    const float* beta1  = (const float*)d_in[11];
    const float* gamma2 = (const float*)d_in[12];
    const float* beta2  = (const float*)d_in[13];
    const float* coeffs = (const float*)d_in[14];
    float* out = (float*)d_out;

    int N = in_sizes[0] / 128;
    int E = in_sizes[1];

    cudaFuncSetAttribute(k_gemm_mma, cudaFuncAttributeMaxDynamicSharedMemorySize, SM_TOT);

    void* p;
    cudaGetSymbolAddress(&p, g_bufB);  float*  bufB  = (float*)p;
    cudaGetSymbolAddress(&p, g_hbufA); __half* hbufA = (__half*)p;
    cudaGetSymbolAddress(&p, g_hbuf);  __half* hbuf  = (__half*)p;
    cudaGetSymbolAddress(&p, g_wpk);   ull*    wpk   = (ull*)p;
    cudaGetSymbolAddress(&p, g_stats); float*  stats = (float*)p;
    cudaGetSymbolAddress(&p, g_scale); float*  scale = (float*)p;
    cudaGetSymbolAddress(&p, g_shift); float*  shift = (float*)p;

    int nb  = (N + 1023) / 1024;
    int eb4 = (E + 1023) / 1024;
    int ab  = (N + 7) / 8;
    int ntiles = (N + 63) / 64;
    int gg = (ntiles < GEMM_GRID) ? ntiles : GEMM_GRID;
    int tb = (N * 32 + 255) / 256;
    float invN = 1.0f / (float)N;

    // CSR build (k_agg = global launch index 3 for ncu)
    k_count<<<eb4, 256>>>(row, E);
    k_scan <<<nb, 256>>>(nb, N);
    k_fill <<<eb4, 256>>>(row, col, ew, E);

    // Layer 1 (b1 cancels in BN)
    k_agg     <<<ab, 256>>>(nf, (uint2*)hbufA, N);
    k_wprep   <<<96, 256>>>(W1, W2, W3);
    k_gemm_mma<<<gg, 256, SM_TOT>>>(hbufA, wpk, nullptr, bufB, N, ntiles);
    k_stats   <<<592, 256>>>(bufB, stats, stats + 128, N);
    k_bnfin   <<<1, 128>>>(stats, stats + 128, gamma1, beta1, scale, shift, invN);
    k_bnpoly_h<<<tb, 256>>>(bufB, hbuf, scale, shift, coeffs, N);

    // Layer 2 (b2 cancels)
    k_agg_h   <<<ab, 256>>>(hbuf, (uint2*)hbufA, N);
    k_gemm_mma<<<gg, 256, SM_TOT>>>(hbufA, wpk + 8192, nullptr, bufB, N, ntiles);
    k_stats   <<<592, 256>>>(bufB, stats + 256, stats + 384, N);
    k_bnfin   <<<1, 128>>>(stats + 256, stats + 384, gamma2, beta2, scale, shift, invN);
    k_bnpoly_h<<<tb, 256>>>(bufB, hbuf, scale, shift, coeffs + 5, N);

    // Layer 3 (bias b3 kept) -> d_out
    k_agg_h   <<<ab, 256>>>(hbuf, (uint2*)hbufA, N);
    k_gemm_mma<<<gg, 256, SM_TOT>>>(hbufA, wpk + 16384, b3, out, N, ntiles);
}

// round 17
// speedup vs baseline: 1.1096x; 1.0771x over previous
#include <cuda_runtime.h>
#include <cuda_fp16.h>
#include <cstdint>

// ---------------------------------------------------------------------------
// PolyActGCN: CSR build -> agg(->fp16) -> GEMM(fp16 A, fp16 W, 1-pass HMMA)
//   -> stats -> bnfin -> bnpoly(->fp16) -> agg_h -> ... -> GEMM(+b3) -> out
// GEMM persistent-CTA (296 blocks, W staged once, 50KB smem, 2 CTA/SM).
// ---------------------------------------------------------------------------

#define NMAX 131072
#define EMAX 2097152
typedef unsigned long long ull;

__device__ float  g_bufB[(size_t)NMAX * 128];    // fp32 GEMM output
__device__ __half g_hbufA[(size_t)NMAX * 128];   // fp16 agg output (GEMM A)
__device__ __half g_hbuf[(size_t)NMAX * 128];    // fp16 activations
__device__ int    g_deg[NMAX];           // invariant: zero at launch entry
__device__ int    g_cur[NMAX];
__device__ int    g_off[NMAX + 1];
__device__ int2   g_edge[EMAX];
__device__ ull    g_epoch;
__device__ ull    g_pub[128];
__device__ ull    g_wpk[3 * 4096];       // [layer][s][nt][lane] fp16x4 b-frags
__device__ float  g_stats[512];          // invariant: zero at launch entry
__device__ float  g_scale[128];
__device__ float  g_shift[128];

// ---------------- helpers --------------------------------------------------
static __device__ __forceinline__ ull pack2(float x, float y) {
    ull p;
    asm("mov.b64 %0, {%1, %2};" : "=l"(p)
        : "r"(__float_as_uint(x)), "r"(__float_as_uint(y)));
    return p;
}
static __device__ __forceinline__ float2 unpack2(ull p) {
    unsigned int a, b;
    asm("mov.b64 {%0, %1}, %2;" : "=r"(a), "=r"(b) : "l"(p));
    return make_float2(__uint_as_float(a), __uint_as_float(b));
}
static __device__ __forceinline__ ull ffma2(ull a, ull b, ull c) {
    ull d;
    asm("fma.rn.f32x2 %0, %1, %2, %3;" : "=l"(d) : "l"(a), "l"(b), "l"(c));
    return d;
}
static __device__ __forceinline__ uint32_t smem_u32(const void* p) {
    uint32_t a;
    asm("{ .reg .u64 t; cvta.to.shared.u64 t, %1; cvt.u32.u64 %0, t; }"
        : "=r"(a) : "l"(p));
    return a;
}

// ---------------- CSR build -----------------------------------------------
__global__ void k_count(const int* __restrict__ row, int E) {
    if (blockIdx.x == 0 && threadIdx.x == 0) atomicAdd(&g_epoch, 1ULL);
    int e = blockIdx.x * 256 + threadIdx.x;
    if (e < E) atomicAdd(&g_deg[__ldcs(&row[e])], 1);
}

__global__ void k_scan(int nb, int N) {
    __shared__ int sh[256];
    __shared__ int bsum[128];
    int b = blockIdx.x, t = threadIdx.x;
    ull epoch = g_epoch;
    int idx = (b << 8) + t;
    int4 d4 = ((const int4*)g_deg)[idx];
    ((int4*)g_deg)[idx] = make_int4(0, 0, 0, 0);
    int s0 = d4.x, s1 = s0 + d4.y, s2 = s1 + d4.z, s3 = s2 + d4.w;
    sh[t] = s3;
    __syncthreads();
    for (int d = 1; d < 256; d <<= 1) {
        int u = (t >= d) ? sh[t - d] : 0;
        __syncthreads();
        sh[t] += u;
        __syncthreads();
    }
    if (t == 0) atomicExch(&g_pub[b], (epoch << 32) | (unsigned)sh[255]);
    if (t < nb) {
        ull v;
        do { v = *(volatile ull*)&g_pub[t]; } while ((v >> 32) != (epoch & 0xffffffffULL));
        bsum[t] = (int)(v & 0xffffffffULL);
    }
    __syncthreads();
    int pre = 0;
    for (int j = 0; j < b; j++) pre += bsum[j];
    if (b == 0 && t == 0) {
        int tot = 0;
        for (int j = 0; j < nb; j++) tot += bsum[j];
        g_off[N] = tot;
    }
    int pr = pre + sh[t] - s3;
    int4 o4 = make_int4(pr, pr + s0, pr + s1, pr + s2);
    ((int4*)g_off)[idx] = o4;
    ((int4*)g_cur)[idx] = o4;
}

__global__ void k_fill(const int* __restrict__ row, const int* __restrict__ col,
                       const float* __restrict__ ew, int E) {
    int e = blockIdx.x * 256 + threadIdx.x;
    if (e < E) {
        int p = atomicAdd(&g_cur[__ldcs(&row[e])], 1);
        g_edge[p] = make_int2(__ldcs(&col[e]), __float_as_int(__ldcs(&ew[e])));
    }
}

// ---------------- aggregation (fp32 source, layer 1) -> fp16 out -----------
__global__ void __launch_bounds__(256)
k_agg(const float* __restrict__ x, uint2* __restrict__ out, int N) {
    int node = (blockIdx.x * 256 + threadIdx.x) >> 5;
    int lane = threadIdx.x & 31;
    if (node >= N) return;
    const char* xb = (const char*)x + ((size_t)lane << 4);
    int i = g_off[node], e = g_off[node + 1];
    ull a00 = 0, a01 = 0, a10 = 0, a11 = 0;
#define ACC(f, wbits, A0, A1)                                       \
    {                                                               \
        float wv = __int_as_float(wbits);                           \
        ull wp = pack2(wv, wv);                                     \
        A0 = ffma2(pack2((f).x, (f).y), wp, A0);                    \
        A1 = ffma2(pack2((f).z, (f).w), wp, A1);                    \
    }
    for (; i + 8 <= e; i += 8) {
        int2 e0 = __ldcs(&g_edge[i]);
        int2 e1 = __ldcs(&g_edge[i + 1]);
        int2 e2 = __ldcs(&g_edge[i + 2]);
        int2 e3 = __ldcs(&g_edge[i + 3]);
        int2 e4 = __ldcs(&g_edge[i + 4]);
        int2 e5 = __ldcs(&g_edge[i + 5]);
        int2 e6 = __ldcs(&g_edge[i + 6]);
        int2 e7 = __ldcs(&g_edge[i + 7]);
        float4 f0 = *(const float4*)(xb + ((size_t)(unsigned)e0.x << 9));
        float4 f1 = *(const float4*)(xb + ((size_t)(unsigned)e1.x << 9));
        float4 f2 = *(const float4*)(xb + ((size_t)(unsigned)e2.x << 9));
        float4 f3 = *(const float4*)(xb + ((size_t)(unsigned)e3.x << 9));
        float4 f4 = *(const float4*)(xb + ((size_t)(unsigned)e4.x << 9));
        float4 f5 = *(const float4*)(xb + ((size_t)(unsigned)e5.x << 9));
        float4 f6 = *(const float4*)(xb + ((size_t)(unsigned)e6.x << 9));
        float4 f7 = *(const float4*)(xb + ((size_t)(unsigned)e7.x << 9));
        ACC(f0, e0.y, a00, a01); ACC(f1, e1.y, a10, a11);
        ACC(f2, e2.y, a00, a01); ACC(f3, e3.y, a10, a11);
        ACC(f4, e4.y, a00, a01); ACC(f5, e5.y, a10, a11);
        ACC(f6, e6.y, a00, a01); ACC(f7, e7.y, a10, a11);
    }
    while (i < e) {
        int m = e - i;
        int2 e0 = __ldcs(&g_edge[i]);
        int2 e1 = __ldcs(&g_edge[i + ((m > 1) ? 1 : 0)]);
        int2 e2 = __ldcs(&g_edge[i + ((m > 2) ? 2 : 0)]);
        int2 e3 = __ldcs(&g_edge[i + ((m > 3) ? 3 : 0)]);
        if (m <= 1) e1.y = 0;
        if (m <= 2) e2.y = 0;
        if (m <= 3) e3.y = 0;
        float4 f0 = *(const float4*)(xb + ((size_t)(unsigned)e0.x << 9));
        float4 f1 = *(const float4*)(xb + ((size_t)(unsigned)e1.x << 9));
        float4 f2 = *(const float4*)(xb + ((size_t)(unsigned)e2.x << 9));
        float4 f3 = *(const float4*)(xb + ((size_t)(unsigned)e3.x << 9));
        ACC(f0, e0.y, a00, a01); ACC(f1, e1.y, a10, a11);
        ACC(f2, e2.y, a00, a01); ACC(f3, e3.y, a10, a11);
        i += 4;
    }
#undef ACC
    float2 ra = unpack2(a00), rb = unpack2(a10);
    float2 ra2 = unpack2(a01), rb2 = unpack2(a11);
    __half2 h01 = __floats2half2_rn(ra.x + rb.x, ra.y + rb.y);
    __half2 h23 = __floats2half2_rn(ra2.x + rb2.x, ra2.y + rb2.y);
    uint2 u;
    u.x = *(uint32_t*)&h01;
    u.y = *(uint32_t*)&h23;
    __stcs(&out[(size_t)node * 32 + lane], u);
}

// ---------------- aggregation (fp16 source, layers 2/3) -> fp16 out --------
__global__ void __launch_bounds__(256)
k_agg_h(const __half* __restrict__ x, uint2* __restrict__ out, int N) {
    int node = (blockIdx.x * 256 + threadIdx.x) >> 5;
    int lane = threadIdx.x & 31;
    if (node >= N) return;
    const char* xb = (const char*)x + ((size_t)lane << 3);
    int i = g_off[node], e = g_off[node + 1];
    ull a00 = 0, a01 = 0, a10 = 0, a11 = 0;
#define ACCH(f, wbits, A0, A1)                                      \
    {                                                               \
        float wv = __int_as_float(wbits);                           \
        ull wp = pack2(wv, wv);                                     \
        float2 p01 = __half22float2(*(const __half2*)&(f).x);       \
        float2 p23 = __half22float2(*(const __half2*)&(f).y);       \
        A0 = ffma2(pack2(p01.x, p01.y), wp, A0);                    \
        A1 = ffma2(pack2(p23.x, p23.y), wp, A1);                    \
    }
    for (; i + 8 <= e; i += 8) {
        int2 e0 = __ldcs(&g_edge[i]);
        int2 e1 = __ldcs(&g_edge[i + 1]);
        int2 e2 = __ldcs(&g_edge[i + 2]);
        int2 e3 = __ldcs(&g_edge[i + 3]);
        int2 e4 = __ldcs(&g_edge[i + 4]);
        int2 e5 = __ldcs(&g_edge[i + 5]);
        int2 e6 = __ldcs(&g_edge[i + 6]);
        int2 e7 = __ldcs(&g_edge[i + 7]);
        uint2 f0 = *(const uint2*)(xb + ((size_t)(unsigned)e0.x << 8));
        uint2 f1 = *(const uint2*)(xb + ((size_t)(unsigned)e1.x << 8));
        uint2 f2 = *(const uint2*)(xb + ((size_t)(unsigned)e2.x << 8));
        uint2 f3 = *(const uint2*)(xb + ((size_t)(unsigned)e3.x << 8));
        uint2 f4 = *(const uint2*)(xb + ((size_t)(unsigned)e4.x << 8));
        uint2 f5 = *(const uint2*)(xb + ((size_t)(unsigned)e5.x << 8));
        uint2 f6 = *(const uint2*)(xb + ((size_t)(unsigned)e6.x << 8));
        uint2 f7 = *(const uint2*)(xb + ((size_t)(unsigned)e7.x << 8));
        ACCH(f0, e0.y, a00, a01); ACCH(f1, e1.y, a10, a11);
        ACCH(f2, e2.y, a00, a01); ACCH(f3, e3.y, a10, a11);
        ACCH(f4, e4.y, a00, a01); ACCH(f5, e5.y, a10, a11);
        ACCH(f6, e6.y, a00, a01); ACCH(f7, e7.y, a10, a11);
    }
    while (i < e) {
        int m = e - i;
        int2 e0 = __ldcs(&g_edge[i]);
        int2 e1 = __ldcs(&g_edge[i + ((m > 1) ? 1 : 0)]);
        int2 e2 = __ldcs(&g_edge[i + ((m > 2) ? 2 : 0)]);
        int2 e3 = __ldcs(&g_edge[i + ((m > 3) ? 3 : 0)]);
        if (m <= 1) e1.y = 0;
        if (m <= 2) e2.y = 0;
        if (m <= 3) e3.y = 0;
        uint2 f0 = *(const uint2*)(xb + ((size_t)(unsigned)e0.x << 8));
        uint2 f1 = *(const uint2*)(xb + ((size_t)(unsigned)e1.x << 8));
        uint2 f2 = *(const uint2*)(xb + ((size_t)(unsigned)e2.x << 8));
        uint2 f3 = *(const uint2*)(xb + ((size_t)(unsigned)e3.x << 8));
        ACCH(f0, e0.y, a00, a01); ACCH(f1, e1.y, a10, a11);
        ACCH(f2, e2.y, a00, a01); ACCH(f3, e3.y, a10, a11);
        i += 4;
    }
#undef ACCH
    float2 ra = unpack2(a00), rb = unpack2(a10);
    float2 ra2 = unpack2(a01), rb2 = unpack2(a11);
    __half2 h01 = __floats2half2_rn(ra.x + rb.x, ra.y + rb.y);
    __half2 h23 = __floats2half2_rn(ra2.x + rb2.x, ra2.y + rb2.y);
    uint2 u;
    u.x = *(uint32_t*)&h01;
    u.y = *(uint32_t*)&h23;
    __stcs(&out[(size_t)node * 32 + lane], u);
}

// ---------------- W prep: fp16, per-lane b-frags ---------------------------
// entry i = [layer(3)][s(8)][nt(16)][lane(32)]
__global__ void k_wprep(const float* __restrict__ W1, const float* __restrict__ W2,
                        const float* __restrict__ W3) {
    int i = blockIdx.x * 256 + threadIdx.x;      // < 12288
    int lane = i & 31, nt = (i >> 5) & 15, s = (i >> 9) & 7;
    int layer = i >> 12;
    const float* W = (layer == 0) ? W1 : (layer == 1) ? W2 : W3;
    int k0 = (s << 4) + ((lane & 3) << 1);
    int n  = (nt << 3) + (lane >> 2);
    __half2 b0, b1;
    b0.x = __float2half_rn(__ldg(&W[(k0 << 7) + n]));
    b0.y = __float2half_rn(__ldg(&W[((k0 + 1) << 7) + n]));
    b1.x = __float2half_rn(__ldg(&W[((k0 + 8) << 7) + n]));
    b1.y = __float2half_rn(__ldg(&W[((k0 + 9) << 7) + n]));
    uint2 pk;
    pk.x = *(uint32_t*)&b0;
    pk.y = *(uint32_t*)&b1;
    g_wpk[i] = *(ull*)&pk;
}

// ---------------- persistent HMMA GEMM (fp16 A, fp16 W, 1 pass) ------------
// grid = min(ntiles,296). smem: A[64x272B]=17408, W=32768 -> 50176B
#define A_STRIDE 272
#define SMA 0
#define SMW 17408
#define SM_TOT 50176
#define GEMM_GRID 296

__global__ void __launch_bounds__(256, 2)
k_gemm_mma(const __half* __restrict__ A, const ull* __restrict__ Wpk,
           const float* __restrict__ bias, float* __restrict__ out,
           int N, int ntiles) {
    extern __shared__ char smem[];
    uint32_t sb = smem_u32(smem);
    int t = threadIdx.x, lane = t & 31, w = t >> 5;

    // stage W once (32KB raw copy)
    {
        const int4* src = (const int4*)Wpk;
        int4* dst = (int4*)(smem + SMW);
        for (int i = t; i < 2048; i += 256) dst[i] = src[i];
    }

    int sub = w & 3, ch = w >> 2;
    uint32_t arow = (uint32_t)((16 * sub + (lane & 7) + ((lane >> 3) & 1) * 8) * A_STRIDE +
                               ((lane >> 4) << 4));
    int c0 = (ch << 6) + ((lane & 3) << 1);
    float bb0 = 0.f, bb1 = 0.f;

    for (int tile = blockIdx.x; tile < ntiles; tile += GEMM_GRID) {
        int row0 = tile << 6;
        // stage A: 64 rows x 16 chunks of 16B (raw fp16 copy, zero-pad tail)
#pragma unroll
        for (int j = 0; j < 4; j++) {
            int i = t + 256 * j;
            int r = i >> 4, chk = i & 15;
            uint4 v = make_uint4(0u, 0u, 0u, 0u);
            if (row0 + r < N)
                v = __ldcs((const uint4*)(A + (size_t)(row0 + r) * 128 + (chk << 3)));
            *(uint4*)(smem + SMA + r * A_STRIDE + (chk << 4)) = v;
        }
        __syncthreads();

        float acc[8][4];
#pragma unroll
        for (int nt = 0; nt < 8; nt++)
#pragma unroll
            for (int c = 0; c < 4; c++) acc[nt][c] = 0.0f;

        uint32_t abase = sb + SMA + arow;
        uint32_t wbase = sb + SMW + (lane << 3) + ((uint32_t)ch << 11);
        for (int s = 0; s < 8; s++) {
            uint32_t a0, a1, a2, a3;
            asm volatile(
                "ldmatrix.sync.aligned.m8n8.x4.shared.b16 {%0,%1,%2,%3}, [%4];"
                : "=r"(a0), "=r"(a1), "=r"(a2), "=r"(a3)
                : "r"(abase + (s << 5)));
            uint32_t wrow = wbase + (s << 12);
#pragma unroll
            for (int nt = 0; nt < 8; nt++) {
                uint32_t b0, b1;
                asm volatile("ld.shared.v2.u32 {%0,%1}, [%2];"
                             : "=r"(b0), "=r"(b1) : "r"(wrow + (nt << 8)));
                asm volatile(
                    "mma.sync.aligned.m16n8k16.row.col.f32.f16.f16.f32 "
                    "{%0,%1,%2,%3}, {%4,%5,%6,%7}, {%8,%9}, {%0,%1,%2,%3};"
                    : "+f"(acc[nt][0]), "+f"(acc[nt][1]),
                      "+f"(acc[nt][2]), "+f"(acc[nt][3])
                    : "r"(a0), "r"(a1), "r"(a2), "r"(a3), "r"(b0), "r"(b1));
            }
        }
        __syncthreads();

        // epilogue
        int gr = (tile << 6) + 16 * sub + (lane >> 2);
        bool val0 = gr < N, val1 = (gr + 8) < N;
        float* o0 = out + (size_t)gr * 128;
        float* o1 = o0 + 8 * 128;
#pragma unroll
        for (int nt = 0; nt < 8; nt++) {
            int col = (nt << 3) + c0;
            if (bias) { bb0 = __ldg(&bias[col]); bb1 = __ldg(&bias[col + 1]); }
            if (val0) *(float2*)(o0 + col) = make_float2(acc[nt][0] + bb0, acc[nt][1] + bb1);
            if (val1) *(float2*)(o1 + col) = make_float2(acc[nt][2] + bb0, acc[nt][3] + bb1);
        }
    }
}

// ---------------- stats / bnfin / bnpoly(->fp16) ---------------------------
__global__ void k_stats(const float* __restrict__ X, float* __restrict__ sum,
                        float* __restrict__ sumsq, int N) {
    __shared__ float s1[256], s2[256];
    int t = threadIdx.x;
    size_t total = (size_t)N * 128;
    float a = 0.f, b = 0.f;
    for (size_t i = (size_t)blockIdx.x * 256 + t; i < total;
         i += (size_t)gridDim.x * 256) {
        float v = X[i];
        a += v;
        b = fmaf(v, v, b);
    }
    s1[t] = a; s2[t] = b;
    __syncthreads();
    if (t < 128) {
        atomicAdd(&sum[t],   s1[t] + s1[t + 128]);
        atomicAdd(&sumsq[t], s2[t] + s2[t + 128]);
    }
}

__global__ void k_bnfin(float* __restrict__ sum, float* __restrict__ sumsq,
                        const float* __restrict__ gamma, const float* __restrict__ beta,
                        float* __restrict__ scale, float* __restrict__ shift, float invN) {
    int t = threadIdx.x;  // 128
    float sm = sum[t], sq = sumsq[t];
    sum[t] = 0.0f;
    sumsq[t] = 0.0f;
    float m = sm * invN;
    float v = fmaf(-m, m, sq * invN);
    float s = gamma[t] * rsqrtf(v + 1e-5f);
    scale[t] = s;
    shift[t] = fmaf(-m, s, beta[t]);
}

__global__ void k_bnpoly_h(const float* __restrict__ X, __half* __restrict__ H,
                           const float* __restrict__ scale, const float* __restrict__ shift,
                           const float* __restrict__ co, int N) {
    int i = blockIdx.x * 256 + threadIdx.x;
    if (i >= N * 32) return;
    int c4 = i & 31;
    float4 sc = *(const float4*)&scale[c4 << 2];
    float4 sh = *(const float4*)&shift[c4 << 2];
    float c0 = __ldg(&co[0]), c1 = __ldg(&co[1]), c2 = __ldg(&co[2]);
    float c3 = __ldg(&co[3]), cl = __ldg(&co[4]);
    float4 v = __ldcs(&((const float4*)X)[i]);
    float x, p;
    x = fmaf(v.x, sc.x, sh.x);
    p = fmaf(cl, x, c3); p = fmaf(p, x, c2); p = fmaf(p, x, c1); v.x = fmaf(p, x, c0);
    x = fmaf(v.y, sc.y, sh.y);
    p = fmaf(cl, x, c3); p = fmaf(p, x, c2); p = fmaf(p, x, c1); v.y = fmaf(p, x, c0);
    x = fmaf(v.z, sc.z, sh.z);
    p = fmaf(cl, x, c3); p = fmaf(p, x, c2); p = fmaf(p, x, c1); v.z = fmaf(p, x, c0);
    x = fmaf(v.w, sc.w, sh.w);
    p = fmaf(cl, x, c3); p = fmaf(p, x, c2); p = fmaf(p, x, c1); v.w = fmaf(p, x, c0);
    __half2 h01 = __floats2half2_rn(v.x, v.y);
    __half2 h23 = __floats2half2_rn(v.z, v.w);
    uint2 u;
    u.x = *(uint32_t*)&h01;
    u.y = *(uint32_t*)&h23;
    ((uint2*)H)[i] = u;
}

// ---------------------------------------------------------------------------
extern "C" void kernel_launch(void* const* d_in, const int* in_sizes, int n_in,
                              void* d_out, int out_size) {
    const float* nf     = (const float*)d_in[0];
    const int*   row    = (const int*)  d_in[1];
    const int*   col    = (const int*)  d_in[2];
    const float* ew     = (const float*)d_in[3];
    const float* W1     = (const float*)d_in[4];
    const float* W2     = (const float*)d_in[6];
    const float* W3     = (const float*)d_in[8];
    const float* b3     = (const float*)d_in[9];
    const float* gamma1 = (const float*)d_in[10];
    const float* beta1  = (const float*)d_in[11];
    const float* gamma2 = (const float*)d_in[12];
    const float* beta2  = (const float*)d_in[13];
    const float* coeffs = (const float*)d_in[14];
    float* out = (float*)d_out;

    int N = in_sizes[0] / 128;
    int E = in_sizes[1];

    cudaFuncSetAttribute(k_gemm_mma, cudaFuncAttributeMaxDynamicSharedMemorySize, SM_TOT);

    void* p;
    cudaGetSymbolAddress(&p, g_bufB);  float*  bufB  = (float*)p;
    cudaGetSymbolAddress(&p, g_hbufA); __half* hbufA = (__half*)p;
    cudaGetSymbolAddress(&p, g_hbuf);  __half* hbuf  = (__half*)p;
    cudaGetSymbolAddress(&p, g_wpk);   ull*    wpk   = (ull*)p;
    cudaGetSymbolAddress(&p, g_stats); float*  stats = (float*)p;
    cudaGetSymbolAddress(&p, g_scale); float*  scale = (float*)p;
    cudaGetSymbolAddress(&p, g_shift); float*  shift = (float*)p;

    int nb = (N + 1023) / 1024;
    int eb = (E + 255) / 256;
    int ab = (N + 7) / 8;
    int ntiles = (N + 63) / 64;
    int gg = (ntiles < GEMM_GRID) ? ntiles : GEMM_GRID;
    int tb = (N * 32 + 255) / 256;
    float invN = 1.0f / (float)N;

    // CSR build (k_agg = global launch index 3 for ncu)
    k_count<<<eb, 256>>>(row, E);
    k_scan <<<nb, 256>>>(nb, N);
    k_fill <<<eb, 256>>>(row, col, ew, E);

    // Layer 1 (b1 cancels in BN)
    k_agg     <<<ab, 256>>>(nf, (uint2*)hbufA, N);
    k_wprep   <<<48, 256>>>(W1, W2, W3);
    k_gemm_mma<<<gg, 256, SM_TOT>>>(hbufA, wpk, nullptr, bufB, N, ntiles);
    k_stats   <<<592, 256>>>(bufB, stats, stats + 128, N);
    k_bnfin   <<<1, 128>>>(stats, stats + 128, gamma1, beta1, scale, shift, invN);
    k_bnpoly_h<<<tb, 256>>>(bufB, hbuf, scale, shift, coeffs, N);

    // Layer 2 (b2 cancels)
    k_agg_h   <<<ab, 256>>>(hbuf, (uint2*)hbufA, N);
    k_gemm_mma<<<gg, 256, SM_TOT>>>(hbufA, wpk + 4096, nullptr, bufB, N, ntiles);
    k_stats   <<<592, 256>>>(bufB, stats + 256, stats + 384, N);
    k_bnfin   <<<1, 128>>>(stats + 256, stats + 384, gamma2, beta2, scale, shift, invN);
    k_bnpoly_h<<<tb, 256>>>(bufB, hbuf, scale, shift, coeffs + 5, N);

    // Layer 3 (bias b3 kept) -> d_out
    k_agg_h   <<<ab, 256>>>(hbuf, (uint2*)hbufA, N);
    k_gemm_mma<<<gg, 256, SM_TOT>>>(hbufA, wpk + 8192, b3, out, N, ntiles);
}